// round 17
// baseline (speedup 1.0000x reference)
#include <cuda_runtime.h>
#include <cuda_fp16.h>
#include <cstdint>

// Problem constants
#define M_DIM 8192
#define N_DIM 4096
#define K_DIM 4096
#define ALPHA 0.01f
#define INPUT_SCALE 0.05f

// ---------------------------------------------------------------------------
// Scratch (no cudaMalloc allowed): fp16 copies of quantized A and W
// ---------------------------------------------------------------------------
__device__ __half g_xh[(size_t)M_DIM * K_DIM];   // 67 MB
__device__ __half g_wh[(size_t)N_DIM * K_DIM];   // 33.5 MB

// ---------------------------------------------------------------------------
// Kernel 0: fused prep — x fp32 -> quantized fp16, weight int32 -> fp16
// ---------------------------------------------------------------------------
#define N4X ((M_DIM * K_DIM) / 4)     // 8388608
#define N4W ((N_DIM * K_DIM) / 4)     // 4194304

__global__ void prep_kernel(const float* __restrict__ x, const int* __restrict__ w32,
                            __half* __restrict__ xh, __half* __restrict__ wh) {
    int i = blockIdx.x * blockDim.x + threadIdx.x;
    if (i < N4X) {
        float4 v = reinterpret_cast<const float4*>(x)[i];
        int q0 = __float2int_rn(__fdiv_rn(v.x, INPUT_SCALE));
        int q1 = __float2int_rn(__fdiv_rn(v.y, INPUT_SCALE));
        int q2 = __float2int_rn(__fdiv_rn(v.z, INPUT_SCALE));
        int q3 = __float2int_rn(__fdiv_rn(v.w, INPUT_SCALE));
        q0 = max(-128, min(127, q0));
        q1 = max(-128, min(127, q1));
        q2 = max(-128, min(127, q2));
        q3 = max(-128, min(127, q3));
        __half2 h0 = __halves2half2(__int2half_rn(q0), __int2half_rn(q1));
        __half2 h1 = __halves2half2(__int2half_rn(q2), __int2half_rn(q3));
        uint2 o;
        o.x = *reinterpret_cast<unsigned*>(&h0);
        o.y = *reinterpret_cast<unsigned*>(&h1);
        reinterpret_cast<uint2*>(xh)[i] = o;
    } else {
        int j = i - N4X;
        if (j >= N4W) return;
        int4 v = reinterpret_cast<const int4*>(w32)[j];
        __half2 h0 = __halves2half2(__int2half_rn(v.x), __int2half_rn(v.y));
        __half2 h1 = __halves2half2(__int2half_rn(v.z), __int2half_rn(v.w));
        uint2 o;
        o.x = *reinterpret_cast<unsigned*>(&h0);
        o.y = *reinterpret_cast<unsigned*>(&h1);
        reinterpret_cast<uint2*>(wh)[j] = o;
    }
}

// ---------------------------------------------------------------------------
// Kernel 1: fp16 GEMM via HMMA m16n8k16 (f32 accum)
//   CTA 128x128, 8 warps 2(M)x4(N), warp tile 64x32, 3-stage cp.async ring,
//   swizzled smem, ldmatrix with REGISTER DOUBLE-BUFFERED fragments
// ---------------------------------------------------------------------------
#define BM 128
#define BN 128
#define BKE 64
#define ROWB 128
#define STAGES 3
#define KT (K_DIM / BKE)              // 64
#define THREADS 256

#define TILE_BYTES (BM * ROWB)        // 16 KB
#define SMEM_STAGE_BYTES (2 * TILE_BYTES)
#define SMEM_TOTAL (STAGES * SMEM_STAGE_BYTES)   // 96 KB -> 2 CTAs/SM

__device__ __forceinline__ uint32_t smem_u32(const void* p) {
    uint32_t a;
    asm("{ .reg .u64 t; cvta.to.shared.u64 t, %1; cvt.u32.u64 %0, t; }" : "=r"(a) : "l"(p));
    return a;
}
__device__ __forceinline__ void cp16(uint32_t saddr, const void* gptr) {
    asm volatile("cp.async.cg.shared.global [%0], [%1], 16;\n" :: "r"(saddr), "l"(gptr));
}
__device__ __forceinline__ void ldsm4(unsigned* r, uint32_t saddr) {
    asm volatile("ldmatrix.sync.aligned.m8n8.x4.shared.b16 {%0,%1,%2,%3}, [%4];"
                 : "=r"(r[0]), "=r"(r[1]), "=r"(r[2]), "=r"(r[3]) : "r"(saddr));
}
__device__ __forceinline__ void mma_f16(float* c, const unsigned* a, const unsigned* b) {
    asm volatile(
        "mma.sync.aligned.m16n8k16.row.col.f32.f16.f16.f32 "
        "{%0,%1,%2,%3}, {%4,%5,%6,%7}, {%8,%9}, {%0,%1,%2,%3};\n"
        : "+f"(c[0]), "+f"(c[1]), "+f"(c[2]), "+f"(c[3])
        : "r"(a[0]), "r"(a[1]), "r"(a[2]), "r"(a[3]),
          "r"(b[0]), "r"(b[1]));
}

__global__ __launch_bounds__(THREADS, 2)
void gemm_f16_kernel(const __half* __restrict__ Ah,
                     const __half* __restrict__ Wh,
                     const float* __restrict__ bias,
                     float* __restrict__ out) {
    extern __shared__ __align__(1024) int8_t smem[];
    const uint32_t sbase = smem_u32(smem);

    const int tid  = threadIdx.x;
    const int bm   = blockIdx.y * BM;
    const int bn   = blockIdx.x * BN;
    const int w    = tid >> 5;
    const int lane = tid & 31;
    const int wm   = (w >> 2) * 64;
    const int wn   = (w & 3) * 32;
    const int g    = lane >> 2;
    const int tg   = lane & 3;

    float acc[4][4][4];
#pragma unroll
    for (int i = 0; i < 4; i++)
#pragma unroll
        for (int j = 0; j < 4; j++)
#pragma unroll
            for (int r = 0; r < 4; r++) acc[i][j][r] = 0.0f;

    const int8_t* gA = reinterpret_cast<const int8_t*>(Ah);
    const int8_t* gB = reinterpret_cast<const int8_t*>(Wh);
    const size_t rowbytes = (size_t)K_DIM * 2;

    auto stA = [&](int s) { return sbase + s * SMEM_STAGE_BYTES; };
    auto stB = [&](int s) { return sbase + s * SMEM_STAGE_BYTES + TILE_BYTES; };

    auto load_stage = [&](int s, int kt) {
        const int8_t* ga = gA + (size_t)bm * rowbytes + (size_t)kt * ROWB;
        const int8_t* gb = gB + (size_t)bn * rowbytes + (size_t)kt * ROWB;
        const uint32_t sa = stA(s), sb = stB(s);
#pragma unroll
        for (int j = 0; j < 4; j++) {
            int c   = j * THREADS + tid;
            int row = c >> 3;
            int col = (c & 7) * 16;
            uint32_t soff = (uint32_t)(row * ROWB + (col ^ ((row & 7) * 16)));
            cp16(sa + soff, ga + (size_t)row * rowbytes + col);
            cp16(sb + soff, gb + (size_t)row * rowbytes + col);
        }
        asm volatile("cp.async.commit_group;\n");
    };

    const int l15 = lane & 15;
    const int chi = (lane & 16) ? 16 : 0;

    // Per-warp constant parts of ldmatrix addresses (row-dependent)
    uint32_t aRow[4], bRow[2];
#pragma unroll
    for (int mt = 0; mt < 4; mt++) {
        int row = wm + mt * 16 + l15;
        aRow[mt] = (uint32_t)(row * ROWB) | 0x80000000u;  // marker-free; offset only
        aRow[mt] = (uint32_t)(row * ROWB);
        aRow[mt] += 0;  // keep simple; swizzle applied per-ks
    }
#pragma unroll
    for (int j = 0; j < 2; j++) {
        int row = wn + j * 16 + l15;
        bRow[j] = (uint32_t)(row * ROWB);
    }
    const uint32_t aSw[4] = {
        (uint32_t)(((wm + 0  + l15) & 7) * 16), (uint32_t)(((wm + 16 + l15) & 7) * 16),
        (uint32_t)(((wm + 32 + l15) & 7) * 16), (uint32_t)(((wm + 48 + l15) & 7) * 16)};
    const uint32_t bSw[2] = {
        (uint32_t)(((wn + 0  + l15) & 7) * 16), (uint32_t)(((wn + 16 + l15) & 7) * 16)};

    // Fragment register double-buffers
    unsigned afr[2][4][4];
    unsigned bfr[2][4][2];

    auto load_frags = [&](int buf, uint32_t sa, uint32_t sb, int ks) {
        const uint32_t colk = (uint32_t)(ks * 32 + chi);
#pragma unroll
        for (int j = 0; j < 2; j++) {
            unsigned t[4];
            ldsm4(t, sb + bRow[j] + (colk ^ bSw[j]));
            bfr[buf][2 * j][0]     = t[0]; bfr[buf][2 * j][1]     = t[2];
            bfr[buf][2 * j + 1][0] = t[1]; bfr[buf][2 * j + 1][1] = t[3];
        }
#pragma unroll
        for (int mt = 0; mt < 4; mt++)
            ldsm4(afr[buf][mt], sa + aRow[mt] + (colk ^ aSw[mt]));
    };

    load_stage(0, 0);
    load_stage(1, 1);

    for (int kt = 0; kt < KT; kt++) {
        const int cur = kt % STAGES;
        asm volatile("cp.async.wait_group 1;\n");
        __syncthreads();
        if (kt + 2 < KT) load_stage((kt + 2) % STAGES, kt + 2);

        const uint32_t sa = stA(cur), sb = stB(cur);
        load_frags(0, sa, sb, 0);
#pragma unroll
        for (int ks = 0; ks < 4; ks++) {
            const int buf = ks & 1;
            if (ks < 3) load_frags(buf ^ 1, sa, sb, ks + 1);
#pragma unroll
            for (int mt = 0; mt < 4; mt++)
#pragma unroll
                for (int nt = 0; nt < 4; nt++)
                    mma_f16(acc[mt][nt], afr[buf][mt], bfr[buf][nt]);
        }
    }

    // Epilogue: y = ALPHA * acc + bias[n]
#pragma unroll
    for (int mt = 0; mt < 4; mt++) {
        const int m0 = bm + wm + mt * 16 + g;
#pragma unroll
        for (int nt = 0; nt < 4; nt++) {
            const int n0 = bn + wn + nt * 8 + tg * 2;
            const float b0 = bias[n0];
            const float b1 = bias[n0 + 1];
            float2 v0, v1;
            v0.x = ALPHA * acc[mt][nt][0] + b0;
            v0.y = ALPHA * acc[mt][nt][1] + b1;
            v1.x = ALPHA * acc[mt][nt][2] + b0;
            v1.y = ALPHA * acc[mt][nt][3] + b1;
            *reinterpret_cast<float2*>(&out[(size_t)m0 * N_DIM + n0])       = v0;
            *reinterpret_cast<float2*>(&out[(size_t)(m0 + 8) * N_DIM + n0]) = v1;
        }
    }
}

// ---------------------------------------------------------------------------
// Launch
// ---------------------------------------------------------------------------
extern "C" void kernel_launch(void* const* d_in, const int* in_sizes, int n_in,
                              void* d_out, int out_size) {
    const float* x    = (const float*)d_in[0];
    const int*   w32  = (const int*)d_in[1];   // weight delivered as int32
    const float* bias = (const float*)d_in[2];
    float*       out  = (float*)d_out;

    __half *xh, *wh;
    cudaGetSymbolAddress((void**)&xh, g_xh);
    cudaGetSymbolAddress((void**)&wh, g_wh);

    cudaFuncSetAttribute(gemm_f16_kernel, cudaFuncAttributeMaxDynamicSharedMemorySize,
                         SMEM_TOTAL);

    {   // 0) fused prep: quantize x -> fp16, pack W -> fp16
        const int total = N4X + N4W;
        prep_kernel<<<(total + 255) / 256, 256>>>(x, w32, xh, wh);
    }
    {   // 1) fp16 HMMA GEMM + dequant epilogue
        dim3 grid(N_DIM / BN, M_DIM / BM);  // (32, 64)
        gemm_f16_kernel<<<grid, THREADS, SMEM_TOTAL>>>(xh, wh, bias, out);
    }
}